// round 11
// baseline (speedup 1.0000x reference)
#include <cuda_runtime.h>
#include <math_constants.h>

#define N 512
#define D 128
#define MARGIN 0.3f
#define APB 4            // anchors per block
#define NBLK (N / APB)   // 128 blocks = one wave
#define TPB 512          // thread t owns column j = t

__device__ double       g_sum  = 0.0;
__device__ int          g_cnt  = 0;
__device__ unsigned int g_done = 0u;

__global__ __launch_bounds__(TPB)
void triplet_onekernel(const float* __restrict__ X,
                       const int* __restrict__ labels,
                       float* __restrict__ out)
{
    __shared__ __align__(16) float sA[APB][D];   // 4 anchor rows
    __shared__ float sna[APB];                   // anchor squared norms
    __shared__ int   slbl[N];
    __shared__ int   npos[APB];
    __shared__ float posA[APB][64];
    __shared__ float wsum[16];
    __shared__ int   wcnt[16];

    const int tid  = threadIdx.x;
    const int lane = tid & 31;
    const int warp = tid >> 5;
    const int i0   = blockIdx.x * APB;

    // ---- Stage labels (one coalesced pass) and init counters
    slbl[tid] = labels[tid];
    if (tid < APB) npos[tid] = 0;

    // ---- Stage 4 anchor rows + norms: warp a handles anchor a
    if (warp < APB) {
        const float4 v = ((const float4*)(X + (i0 + warp) * D))[lane];
        ((float4*)sA[warp])[lane] = v;
        float s = v.x * v.x + v.y * v.y + v.z * v.z + v.w * v.w;
        #pragma unroll
        for (int o = 16; o > 0; o >>= 1)
            s += __shfl_xor_sync(0xffffffffu, s, o);
        if (lane == 0) sna[warp] = s;
    }
    __syncthreads();

    // ---- Distance row compute: thread t owns j = t.
    // dot(anchor_a, x_j) for a<4 plus |x_j|^2, anchors from broadcast LDS.
    const int j = tid;
    const float4* __restrict__ Xj = (const float4*)(X + j * D);
    float acc0 = 0.f, acc1 = 0.f, acc2 = 0.f, acc3 = 0.f, nj = 0.f;
    #pragma unroll 8
    for (int c = 0; c < D / 4; c++) {
        const float4 v  = Xj[c];                       // scattered LDG, L2-hot
        const float4 a0 = ((const float4*)sA[0])[c];   // broadcast LDS
        const float4 a1 = ((const float4*)sA[1])[c];
        const float4 a2 = ((const float4*)sA[2])[c];
        const float4 a3 = ((const float4*)sA[3])[c];
        acc0 += v.x * a0.x + v.y * a0.y + v.z * a0.z + v.w * a0.w;
        acc1 += v.x * a1.x + v.y * a1.y + v.z * a1.z + v.w * a1.w;
        acc2 += v.x * a2.x + v.y * a2.y + v.z * a2.z + v.w * a2.w;
        acc3 += v.x * a3.x + v.y * a3.y + v.z * a3.z + v.w * a3.w;
        nj   += v.x * v.x  + v.y * v.y  + v.z * v.z  + v.w * v.w;
    }

    float dist[APB];
    dist[0] = sqrtf(fmaxf(sna[0] + nj - 2.0f * acc0, 0.0f));
    dist[1] = sqrtf(fmaxf(sna[1] + nj - 2.0f * acc1, 0.0f));
    dist[2] = sqrtf(fmaxf(sna[2] + nj - 2.0f * acc2, 0.0f));
    dist[3] = sqrtf(fmaxf(sna[3] + nj - 2.0f * acc3, 0.0f));

    // ---- Positive compaction per anchor (few atomics; classes ~10 wide)
    const int lj = slbl[j];
    float dn[APB];
    #pragma unroll
    for (int a = 0; a < APB; a++) {
        const int la = slbl[i0 + a];                  // broadcast LDS
        const bool isPos = (lj == la) && (j != i0 + a);
        if (isPos) {
            const int s = atomicAdd(&npos[a], 1);
            if (s < 64) posA[a][s] = dist[a] + MARGIN;
        }
        dn[a] = (lj != la) ? dist[a] : CUDART_INF_F;  // masked -> relu & cnt 0
    }
    __syncthreads();

    // ---- Triplet accumulation: thread j is the negative; loop positives.
    float lsum = 0.0f;
    int   lcnt = 0;
    #pragma unroll
    for (int a = 0; a < APB; a++) {
        int np = npos[a];
        if (np > 64) np = 64;
        const float dneg = dn[a];
        for (int p = 0; p < np; p++) {
            const float t = posA[a][p] - dneg;        // broadcast LDS
            if (t > 0.0f)    lsum += t;
            if (t > 1e-16f)  lcnt += 1;
        }
    }

    // ---- Block reduce (16 warps)
    #pragma unroll
    for (int o = 16; o > 0; o >>= 1) {
        lsum += __shfl_xor_sync(0xffffffffu, lsum, o);
        lcnt += __shfl_xor_sync(0xffffffffu, lcnt, o);
    }
    if (lane == 0) { wsum[warp] = lsum; wcnt[warp] = lcnt; }
    __syncthreads();

    if (warp == 0) {
        float s = (lane < 16) ? wsum[lane] : 0.0f;
        int   c = (lane < 16) ? wcnt[lane] : 0;
        #pragma unroll
        for (int o = 8; o > 0; o >>= 1) {
            s += __shfl_xor_sync(0xffffffffu, s, o);
            c += __shfl_xor_sync(0xffffffffu, c, o);
        }
        if (lane == 0) {
            atomicAdd(&g_sum, (double)s);
            atomicAdd(&g_cnt, c);
            __threadfence();
            const unsigned ticket = atomicAdd(&g_done, 1u);
            if (ticket == (unsigned)(NBLK - 1)) {
                const double S = atomicAdd(&g_sum, 0.0);
                const int    C = atomicAdd(&g_cnt, 0);
                out[0] = (float)(S / ((double)C + 1e-16));
                // reset for next graph replay (all blocks done with globals)
                g_sum  = 0.0;
                g_cnt  = 0;
                g_done = 0u;
            }
        }
    }
}

extern "C" void kernel_launch(void* const* d_in, const int* in_sizes, int n_in,
                              void* d_out, int out_size) {
    const float* X      = (const float*)d_in[0];   // [512, 128] fp32
    const int*   labels = (const int*)d_in[1];     // [512] int32
    float*       out    = (float*)d_out;           // scalar fp32

    triplet_onekernel<<<NBLK, TPB>>>(X, labels, out);
}

// round 12
// speedup vs baseline: 1.4298x; 1.4298x over previous
#include <cuda_runtime.h>
#include <math_constants.h>

#define N 512
#define D 128
#define MARGIN 0.3f
#define APB 4            // anchors per block
#define NBLK (N / APB)   // 128 blocks = one wave
#define TPB 512          // thread t owns row j = t
#define NF4 (D / 4)      // 32 float4 per row
#define SMEM_DYN (N * 32 * 4)   // 512 rows x 32 floats per col-tile = 64KB

__device__ double       g_sum  = 0.0;
__device__ int          g_cnt  = 0;
__device__ unsigned int g_done = 0u;

__global__ __launch_bounds__(TPB)
void triplet_onekernel(const float* __restrict__ X,
                       const int* __restrict__ labels,
                       float* __restrict__ out)
{
    extern __shared__ __align__(16) float sX[];   // [512][32] j-major, XOR-swizzled

    __shared__ float4 sA4[APB][NF4];   // 4 anchor rows
    __shared__ float  sna[APB];        // anchor squared norms
    __shared__ int    slbl[N];
    __shared__ int    npos[APB];
    __shared__ float  posA[APB][64];
    __shared__ float  wsum[16];
    __shared__ int    wcnt[16];

    const int tid  = threadIdx.x;
    const int lane = tid & 31;
    const int warp = tid >> 5;
    const int i0   = blockIdx.x * APB;

    slbl[tid] = labels[tid];
    if (tid < APB) npos[tid] = 0;

    // anchors -> smem (warp a loads anchor a; one float4 per lane)
    if (warp < APB)
        sA4[warp][lane] = ((const float4*)(X + (i0 + warp) * D))[lane];

    // Per-thread staging geometry (constant across tiles):
    // idx = v*512 + tid; r = idx>>3 (row), f = idx&7 (chunk-in-tile).
    // lanes 0-7 share r, f=0..7 -> one 128B line per 8 lanes (coalesced).
    const float4* __restrict__ X4 = (const float4*)X;
    int gofs[8], sofs[8];
    #pragma unroll
    for (int v = 0; v < 8; v++) {
        const int idx = v * TPB + tid;
        const int r = idx >> 3, f = idx & 7;
        gofs[v] = r * NF4 + f;                 // + t*8 per tile
        sofs[v] = r * 8 + (f ^ (r & 7));       // XOR swizzle slot (float4 units)
    }

    // prefetch tile 0
    float4 pf[8];
    #pragma unroll
    for (int v = 0; v < 8; v++) pf[v] = X4[gofs[v]];

    float acc0 = 0.f, acc1 = 0.f, acc2 = 0.f, acc3 = 0.f, nj = 0.f;
    float4* __restrict__ sX4 = (float4*)sX;

    #pragma unroll
    for (int t = 0; t < 4; t++) {
        __syncthreads();                        // buf free from previous readers
        #pragma unroll
        for (int v = 0; v < 8; v++) sX4[sofs[v]] = pf[v];
        __syncthreads();                        // tile visible

        if (t < 3) {                            // prefetch next tile (hides LDG)
            #pragma unroll
            for (int v = 0; v < 8; v++) pf[v] = X4[gofs[v] + (t + 1) * 8];
        }

        // compute: thread j reads its own row, conflict-free LDS.128
        const int jb = tid * 8, js = tid & 7;
        #pragma unroll
        for (int c4 = 0; c4 < 8; c4++) {
            const float4 xv = sX4[jb + (c4 ^ js)];
            const float4 a0 = sA4[0][t * 8 + c4];   // broadcast
            const float4 a1 = sA4[1][t * 8 + c4];
            const float4 a2 = sA4[2][t * 8 + c4];
            const float4 a3 = sA4[3][t * 8 + c4];
            acc0 += xv.x * a0.x + xv.y * a0.y + xv.z * a0.z + xv.w * a0.w;
            acc1 += xv.x * a1.x + xv.y * a1.y + xv.z * a1.z + xv.w * a1.w;
            acc2 += xv.x * a2.x + xv.y * a2.y + xv.z * a2.z + xv.w * a2.w;
            acc3 += xv.x * a3.x + xv.y * a3.y + xv.z * a3.z + xv.w * a3.w;
            nj   += xv.x * xv.x + xv.y * xv.y + xv.z * xv.z + xv.w * xv.w;
        }
    }

    // anchor norms: the owning thread's nj IS the anchor norm
    const int da = tid - i0;
    if (da >= 0 && da < APB) sna[da] = nj;
    __syncthreads();

    float dist[APB];
    dist[0] = sqrtf(fmaxf(sna[0] + nj - 2.0f * acc0, 0.0f));
    dist[1] = sqrtf(fmaxf(sna[1] + nj - 2.0f * acc1, 0.0f));
    dist[2] = sqrtf(fmaxf(sna[2] + nj - 2.0f * acc2, 0.0f));
    dist[3] = sqrtf(fmaxf(sna[3] + nj - 2.0f * acc3, 0.0f));

    // ---- positive compaction per anchor (few smem atomics; classes ~10 wide)
    const int j  = tid;
    const int lj = slbl[j];
    float dn[APB];
    #pragma unroll
    for (int a = 0; a < APB; a++) {
        const int la = slbl[i0 + a];               // broadcast LDS
        const bool isPos = (lj == la) && (j != i0 + a);
        if (isPos) {
            const int s = atomicAdd(&npos[a], 1);
            if (s < 64) posA[a][s] = dist[a] + MARGIN;
        }
        dn[a] = (lj != la) ? dist[a] : CUDART_INF_F;  // masked -> relu & cnt 0
    }
    __syncthreads();

    // ---- triplet accumulation: thread j is the negative; loop positives
    float lsum = 0.0f;
    int   lcnt = 0;
    #pragma unroll
    for (int a = 0; a < APB; a++) {
        int np = npos[a];
        if (np > 64) np = 64;
        const float dneg = dn[a];
        for (int p = 0; p < np; p++) {
            const float t = posA[a][p] - dneg;      // broadcast LDS
            if (t > 0.0f)    lsum += t;
            if (t > 1e-16f)  lcnt += 1;
        }
    }

    // ---- block reduce (16 warps)
    #pragma unroll
    for (int o = 16; o > 0; o >>= 1) {
        lsum += __shfl_xor_sync(0xffffffffu, lsum, o);
        lcnt += __shfl_xor_sync(0xffffffffu, lcnt, o);
    }
    if (lane == 0) { wsum[warp] = lsum; wcnt[warp] = lcnt; }
    __syncthreads();

    if (warp == 0) {
        float s = (lane < 16) ? wsum[lane] : 0.0f;
        int   c = (lane < 16) ? wcnt[lane] : 0;
        #pragma unroll
        for (int o = 8; o > 0; o >>= 1) {
            s += __shfl_xor_sync(0xffffffffu, s, o);
            c += __shfl_xor_sync(0xffffffffu, c, o);
        }
        if (lane == 0) {
            atomicAdd(&g_sum, (double)s);
            atomicAdd(&g_cnt, c);
            __threadfence();
            const unsigned ticket = atomicAdd(&g_done, 1u);
            if (ticket == (unsigned)(NBLK - 1)) {
                const double S = atomicAdd(&g_sum, 0.0);
                const int    C = atomicAdd(&g_cnt, 0);
                out[0] = (float)(S / ((double)C + 1e-16));
                // reset for next graph replay (all blocks done with globals)
                g_sum  = 0.0;
                g_cnt  = 0;
                g_done = 0u;
            }
        }
    }
}

extern "C" void kernel_launch(void* const* d_in, const int* in_sizes, int n_in,
                              void* d_out, int out_size) {
    const float* X      = (const float*)d_in[0];   // [512, 128] fp32
    const int*   labels = (const int*)d_in[1];     // [512] int32
    float*       out    = (float*)d_out;           // scalar fp32

    cudaFuncSetAttribute(triplet_onekernel,
                         cudaFuncAttributeMaxDynamicSharedMemorySize, SMEM_DYN);
    triplet_onekernel<<<NBLK, TPB, SMEM_DYN>>>(X, labels, out);
}